// round 2
// baseline (speedup 1.0000x reference)
#include <cuda_runtime.h>
#include <cstddef>

// Problem shape (fixed for this dataset entry)
#define Bc 16
#define Tc 1024
#define Cc 1024
#define Mc (Bc * Tc)   // 16384 rows

// Scratch: k, r (=v), and gated wkv output. __device__ globals (no cudaMalloc allowed).
__device__ float g_k[(size_t)Mc * Cc];
__device__ float g_r[(size_t)Mc * Cc];
__device__ float g_o[(size_t)Mc * Cc];

// ---------------------------------------------------------------------------
// NT GEMM: C[M,N] = A[M,K] * B[N,K]^T  (both operands K-contiguous, row-major)
// Block tile 128x128, K-step 8, 256 threads, 8x8 register tile per thread.
// blockIdx.z selects (B0,C0) or (B1,C1) so k and r GEMMs share one launch.
// ---------------------------------------------------------------------------
__global__ __launch_bounds__(256, 2)
void gemm_nt_kernel(const float* __restrict__ A,
                    const float* __restrict__ B0,
                    const float* __restrict__ B1,
                    float* __restrict__ C0,
                    float* __restrict__ C1,
                    int K, int N)
{
    const float* Bmat = (blockIdx.z == 0) ? B0 : B1;
    float*       Cmat = (blockIdx.z == 0) ? C0 : C1;

    __shared__ float As[8][132];   // [k][m], padded stride 132 (16B-aligned rows)
    __shared__ float Bs[8][132];   // [k][n]

    const int tid = threadIdx.x;
    const int tx  = tid & 15;      // 0..15 -> n sub-tile
    const int ty  = tid >> 4;      // 0..15 -> m sub-tile
    const int m0  = blockIdx.y * 128;
    const int n0  = blockIdx.x * 128;

    // Global->shared: each thread loads one float4 of A and of B per K-step.
    const int lrow = tid >> 1;           // 0..127
    const int lk   = (tid & 1) << 2;     // 0 or 4
    const float* Ap = A    + (size_t)(m0 + lrow) * K + lk;
    const float* Bp = Bmat + (size_t)(n0 + lrow) * K + lk;

    float acc[8][8];
#pragma unroll
    for (int i = 0; i < 8; i++)
#pragma unroll
        for (int j = 0; j < 8; j++) acc[i][j] = 0.f;

    for (int k0 = 0; k0 < K; k0 += 8) {
        float4 av = *(const float4*)(Ap + k0);
        float4 bv = *(const float4*)(Bp + k0);
        __syncthreads();   // previous tile's compute done before overwrite
        As[lk + 0][lrow] = av.x;
        As[lk + 1][lrow] = av.y;
        As[lk + 2][lrow] = av.z;
        As[lk + 3][lrow] = av.w;
        Bs[lk + 0][lrow] = bv.x;
        Bs[lk + 1][lrow] = bv.y;
        Bs[lk + 2][lrow] = bv.z;
        Bs[lk + 3][lrow] = bv.w;
        __syncthreads();

#pragma unroll
        for (int kk = 0; kk < 8; kk++) {
            float a[8], b[8];
            *(float4*)(a)     = *(const float4*)(&As[kk][ty * 8]);
            *(float4*)(a + 4) = *(const float4*)(&As[kk][ty * 8 + 4]);
            *(float4*)(b)     = *(const float4*)(&Bs[kk][tx * 8]);
            *(float4*)(b + 4) = *(const float4*)(&Bs[kk][tx * 8 + 4]);
#pragma unroll
            for (int i = 0; i < 8; i++)
#pragma unroll
                for (int j = 0; j < 8; j++)
                    acc[i][j] = fmaf(a[i], b[j], acc[i][j]);
        }
    }

#pragma unroll
    for (int i = 0; i < 8; i++) {
        float* Crow = Cmat + (size_t)(m0 + ty * 8 + i) * N + n0 + tx * 8;
        *(float4*)(Crow)     = make_float4(acc[i][0], acc[i][1], acc[i][2], acc[i][3]);
        *(float4*)(Crow + 4) = make_float4(acc[i][4], acc[i][5], acc[i][6], acc[i][7]);
    }
}

// ---------------------------------------------------------------------------
// WKV scan, direct (non-log-max) form. One thread per (batch, channel) lane.
// Mathematically identical to the reference's max-stabilized scan; with
// |k| <~ 3.5 and per-step decay exp(-exp(td)) in (0,1), running sums stay
// well inside fp32 range. Writes o = sigmoid(r) * y.
// ---------------------------------------------------------------------------
__global__ void wkv_kernel(const float* __restrict__ kbuf,
                           const float* __restrict__ rbuf,
                           const float* __restrict__ td,
                           const float* __restrict__ tf,
                           float* __restrict__ obuf)
{
    const int idx = blockIdx.x * blockDim.x + threadIdx.x;
    if (idx >= Bc * Cc) return;
    const int c = idx & (Cc - 1);
    const int b = idx >> 10;           // Cc == 1024

    const float ew = __expf(-__expf(td[c]));   // exp(w), w = -exp(time_decay)
    const float eu = __expf(tf[c]);            // exp(u)

    const float* kp = kbuf + (size_t)b * Tc * Cc + c;
    const float* rp = rbuf + (size_t)b * Tc * Cc + c;
    float*       op = obuf + (size_t)b * Tc * Cc + c;

    float num = 0.f, den = 0.f;

    for (int t = 0; t < Tc; t += 4) {
        float kt[4], rt[4];
#pragma unroll
        for (int j = 0; j < 4; j++) {          // batched loads -> MLP=8
            kt[j] = kp[(size_t)(t + j) * Cc];
            rt[j] = rp[(size_t)(t + j) * Cc];
        }
#pragma unroll
        for (int j = 0; j < 4; j++) {
            const float ek  = __expf(kt[j]);
            const float euk = eu * ek;
            const float y   = __fdividef(fmaf(euk, rt[j], num), den + euk);
            num = fmaf(ew, num, ek * rt[j]);
            den = fmaf(ew, den, ek);
            const float sg  = __fdividef(1.f, 1.f + __expf(-rt[j]));
            op[(size_t)(t + j) * Cc] = sg * y;
        }
    }
}

// ---------------------------------------------------------------------------
// Launch: gemm(k,r) -> wkv scan -> gemm(out). Default stream, graph-capturable.
// ---------------------------------------------------------------------------
extern "C" void kernel_launch(void* const* d_in, const int* in_sizes, int n_in,
                              void* d_out, int out_size)
{
    const float* x  = (const float*)d_in[0];
    const float* Wk = (const float*)d_in[1];
    const float* Wr = (const float*)d_in[2];
    const float* Wo = (const float*)d_in[3];
    const float* td = (const float*)d_in[4];
    const float* tf = (const float*)d_in[5];
    float* out = (float*)d_out;

    float *pk, *pr, *po;
    cudaGetSymbolAddress((void**)&pk, g_k);
    cudaGetSymbolAddress((void**)&pr, g_r);
    cudaGetSymbolAddress((void**)&po, g_o);

    // k = x * Wk^T ; r = x * Wr^T   (fused via z-dim)
    dim3 grid_kr(Cc / 128, Mc / 128, 2);
    gemm_nt_kernel<<<grid_kr, 256>>>(x, Wk, Wr, pk, pr, Cc, Cc);

    // o = sigmoid(r) * wkv(w, u, k, v=r)
    wkv_kernel<<<(Bc * Cc) / 256, 256>>>(pk, pr, td, tf, po);

    // out = o * Wo^T
    dim3 grid_o(Cc / 128, Mc / 128, 1);
    gemm_nt_kernel<<<grid_o, 256>>>(po, Wo, Wo, out, out, Cc, Cc);
}

// round 4
// speedup vs baseline: 2.5426x; 2.5426x over previous
#include <cuda_runtime.h>
#include <cuda_bf16.h>
#include <cstdint>
#include <cstddef>

// Problem shape (fixed)
#define Bc 16
#define Tc 1024
#define Cc 1024
#define Kc 1024
#define Mc (Bc * Tc)   // 16384

// ---------------------------------------------------------------------------
// Scratch (__device__ globals; no cudaMalloc allowed)
// ---------------------------------------------------------------------------
__device__ __nv_bfloat16 g_xhi[(size_t)Mc * Kc];
__device__ __nv_bfloat16 g_xlo[(size_t)Mc * Kc];
__device__ __nv_bfloat16 g_ohi[(size_t)Mc * Kc];
__device__ __nv_bfloat16 g_olo[(size_t)Mc * Kc];
__device__ float         g_k  [(size_t)Mc * Cc];
__device__ float         g_r  [(size_t)Mc * Cc];
__device__ __nv_bfloat16 g_wkhi[Cc * Kc], g_wklo[Cc * Kc];
__device__ __nv_bfloat16 g_wrhi[Cc * Kc], g_wrlo[Cc * Kc];
__device__ __nv_bfloat16 g_wohi[Cc * Kc], g_wolo[Cc * Kc];

// ---------------------------------------------------------------------------
// Base-ISA PTX helpers (work on .target sm_103 without the 'a' suffix)
// ---------------------------------------------------------------------------
__device__ __forceinline__ uint32_t smem_u32(const void* p) {
    uint32_t a;
    asm("{ .reg .u64 t; cvta.to.shared.u64 t, %1; cvt.u32.u64 %0, t; }"
        : "=r"(a) : "l"(p));
    return a;
}

__device__ __forceinline__ void cp_async16(uint32_t dst, const void* src) {
    asm volatile("cp.async.cg.shared.global [%0], [%1], 16;"
                 :: "r"(dst), "l"(src));
}
__device__ __forceinline__ void cp_commit() {
    asm volatile("cp.async.commit_group;");
}
__device__ __forceinline__ void cp_wait_all() {
    asm volatile("cp.async.wait_group 0;" ::: "memory");
}

__device__ __forceinline__ void ldm_x4(uint32_t* r, uint32_t addr) {
    asm volatile("ldmatrix.sync.aligned.m8n8.x4.shared.b16 {%0,%1,%2,%3}, [%4];"
                 : "=r"(r[0]), "=r"(r[1]), "=r"(r[2]), "=r"(r[3]) : "r"(addr));
}

__device__ __forceinline__ void mma_bf16(float* d, const uint32_t* a,
                                         const uint32_t* b) {
    asm volatile(
        "mma.sync.aligned.m16n8k16.row.col.f32.bf16.bf16.f32 "
        "{%0,%1,%2,%3}, {%4,%5,%6,%7}, {%8,%9}, {%0,%1,%2,%3};"
        : "+f"(d[0]), "+f"(d[1]), "+f"(d[2]), "+f"(d[3])
        : "r"(a[0]), "r"(a[1]), "r"(a[2]), "r"(a[3]), "r"(b[0]), "r"(b[1]));
}

// ---------------------------------------------------------------------------
// fp32 -> (bf16 hi, bf16 lo) split, vectorized
// ---------------------------------------------------------------------------
__global__ void split_kernel(const float* __restrict__ src,
                             __nv_bfloat16* __restrict__ hi,
                             __nv_bfloat16* __restrict__ lo, int n4)
{
    int i = blockIdx.x * blockDim.x + threadIdx.x;
    if (i >= n4) return;
    float4 v = reinterpret_cast<const float4*>(src)[i];
    float vv[4] = {v.x, v.y, v.z, v.w};
    __nv_bfloat16 h[4], l[4];
#pragma unroll
    for (int j = 0; j < 4; j++) {
        h[j] = __float2bfloat16(vv[j]);
        l[j] = __float2bfloat16(vv[j] - __bfloat162float(h[j]));
    }
    __nv_bfloat162 h0; h0.x = h[0]; h0.y = h[1];
    __nv_bfloat162 h1; h1.x = h[2]; h1.y = h[3];
    __nv_bfloat162 l0; l0.x = l[0]; l0.y = l[1];
    __nv_bfloat162 l1; l1.x = l[2]; l1.y = l[3];
    reinterpret_cast<__nv_bfloat162*>(hi)[2 * i]     = h0;
    reinterpret_cast<__nv_bfloat162*>(hi)[2 * i + 1] = h1;
    reinterpret_cast<__nv_bfloat162*>(lo)[2 * i]     = l0;
    reinterpret_cast<__nv_bfloat162*>(lo)[2 * i + 1] = l1;
}

// ---------------------------------------------------------------------------
// HMMA split-bf16 NT GEMM: C[M,N] = A[M,K] * B[N,K]^T (fp32-grade accuracy)
// CTA tile 128x128, K-chunk 64 (128B rows, SW128 xor swizzle), 8 warps in a
// 4(m) x 2(n) grid -> warp tile 32x64. cp.async double buffer.
// blockIdx.z selects (B0,C0)/(B1,C1) so k and r GEMMs share one launch.
// ---------------------------------------------------------------------------
#define BK 64
#define TILE_B 16384                 // 128 rows * 128 bytes
#define STAGE_B (4 * TILE_B)         // Ahi, Alo, Bhi, Blo
#define GEMM_SMEM (2 * STAGE_B)      // 131072 B

__global__ __launch_bounds__(256)
void gemm_hmma(const __nv_bfloat16* __restrict__ Ahi,
               const __nv_bfloat16* __restrict__ Alo,
               const __nv_bfloat16* __restrict__ B0hi,
               const __nv_bfloat16* __restrict__ B0lo,
               const __nv_bfloat16* __restrict__ B1hi,
               const __nv_bfloat16* __restrict__ B1lo,
               float* __restrict__ C0, float* __restrict__ C1)
{
    extern __shared__ char smem_raw[];
    const uint32_t sbase = smem_u32(smem_raw);

    const int tid = threadIdx.x;
    const int wid = tid >> 5;
    const int lane = tid & 31;

    const __nv_bfloat16* Bhi = blockIdx.z ? B1hi : B0hi;
    const __nv_bfloat16* Blo = blockIdx.z ? B1lo : B0lo;
    float* Cmat              = blockIdx.z ? C1   : C0;

    const int m0 = blockIdx.y * 128;
    const int n0 = blockIdx.x * 128;

    // ---- per-thread cp.async source/dst precompute -------------------------
    // 4096 16B segments per stage: mat(4) x row(128) x seg(8). 16 per thread.
    const __nv_bfloat16* srcs[4] = {
        Ahi + (size_t)m0 * Kc, Alo + (size_t)m0 * Kc,
        Bhi + (size_t)n0 * Kc, Blo + (size_t)n0 * Kc
    };

    const __nv_bfloat16* gsrc[16];
    uint32_t sdst[16];
#pragma unroll
    for (int i = 0; i < 16; i++) {
        const int sid = i * 256 + tid;
        const int mat = sid >> 10;
        const int row = (sid >> 3) & 127;
        const int s   = sid & 7;
        gsrc[i] = srcs[mat] + (size_t)row * Kc + s * 8;
        sdst[i] = mat * TILE_B + row * 128 + ((s ^ (row & 7)) << 4);
    }

    // ---- warp tiling -------------------------------------------------------
    const int wm = (wid & 3) * 32;   // warp m offset in CTA tile
    const int wn = (wid >> 2) * 64;  // warp n offset

    float acc[2][8][4];
#pragma unroll
    for (int mi = 0; mi < 2; mi++)
#pragma unroll
        for (int ni = 0; ni < 8; ni++)
#pragma unroll
            for (int j = 0; j < 4; j++) acc[mi][ni][j] = 0.f;

    // ldmatrix base addresses (row+seg lane mapping, swizzled)
    // A frag (m16 x k16): lanes 0-15 rows m, lanes 16-31 second k8 segment
    const int a_row = wm + (lane & 15);          // + mi*16
    const int a_ks  = lane >> 4;                 // 0/1 -> +ks*2
    // B frag (n16 x k16): lanes {0-7,16-23} rows n(+0/+8), {8-15,24-31} k8 seg
    const int b_row = wn + (lane & 7) + ((lane >> 4) << 3);   // + ni*16
    const int b_ks  = (lane >> 3) & 1;

    // prologue: issue chunk 0
#pragma unroll
    for (int i = 0; i < 16; i++) cp_async16(sbase + sdst[i], gsrc[i]);
    cp_commit();

    for (int c = 0; c < Kc / BK; ++c) {
        const uint32_t buf = sbase + (c & 1) * STAGE_B;
        cp_wait_all();
        __syncthreads();

        if (c + 1 < Kc / BK) {
            const uint32_t nbuf = sbase + ((c + 1) & 1) * STAGE_B;
            const int koff = (c + 1) * BK;
#pragma unroll
            for (int i = 0; i < 16; i++)
                cp_async16(nbuf + sdst[i], gsrc[i] + koff);
            cp_commit();
        }

#pragma unroll
        for (int ks = 0; ks < 4; ks++) {
            // load A fragments (hi, lo) for mi = 0,1
            uint32_t afh[2][4], afl[2][4];
#pragma unroll
            for (int mi = 0; mi < 2; mi++) {
                const int row = a_row + mi * 16;
                const int sg  = (ks * 2 + a_ks) ^ (row & 7);
                const uint32_t off = row * 128 + (sg << 4);
                ldm_x4(afh[mi], buf + 0 * TILE_B + off);
                ldm_x4(afl[mi], buf + 1 * TILE_B + off);
            }
            // load B fragments (hi, lo) for ni16 = 0..3
            uint32_t bfh[4][4], bfl[4][4];
#pragma unroll
            for (int ni = 0; ni < 4; ni++) {
                const int row = b_row + ni * 16;
                const int sg  = (ks * 2 + b_ks) ^ (row & 7);
                const uint32_t off = row * 128 + (sg << 4);
                ldm_x4(bfh[ni], buf + 2 * TILE_B + off);
                ldm_x4(bfl[ni], buf + 3 * TILE_B + off);
            }
            // MMAs: hi*hi + hi*lo + lo*hi
#pragma unroll
            for (int mi = 0; mi < 2; mi++)
#pragma unroll
                for (int ni = 0; ni < 4; ni++) {
                    mma_bf16(acc[mi][2 * ni],     afh[mi], &bfh[ni][0]);
                    mma_bf16(acc[mi][2 * ni + 1], afh[mi], &bfh[ni][2]);
                    mma_bf16(acc[mi][2 * ni],     afh[mi], &bfl[ni][0]);
                    mma_bf16(acc[mi][2 * ni + 1], afh[mi], &bfl[ni][2]);
                    mma_bf16(acc[mi][2 * ni],     afl[mi], &bfh[ni][0]);
                    mma_bf16(acc[mi][2 * ni + 1], afl[mi], &bfh[ni][2]);
                }
        }
        __syncthreads();   // keep buffer lifetimes aligned across warps
    }

    // ---- epilogue ----------------------------------------------------------
    const int er = lane >> 2;          // 0..7
    const int ec = (lane & 3) * 2;     // 0,2,4,6
#pragma unroll
    for (int mi = 0; mi < 2; mi++) {
        const int mb = m0 + wm + mi * 16;
#pragma unroll
        for (int ni = 0; ni < 8; ni++) {
            const int nb = n0 + wn + ni * 8;
            float2 v0 = make_float2(acc[mi][ni][0], acc[mi][ni][1]);
            float2 v1 = make_float2(acc[mi][ni][2], acc[mi][ni][3]);
            *reinterpret_cast<float2*>(Cmat + (size_t)(mb + er) * Cc + nb + ec) = v0;
            *reinterpret_cast<float2*>(Cmat + (size_t)(mb + 8 + er) * Cc + nb + ec) = v1;
        }
    }
}

// ---------------------------------------------------------------------------
// WKV scan (direct form; numerically safe: decay<1, |k|<~4).
// Writes o = sigmoid(r) * y directly as (bf16 hi, bf16 lo) split.
// ---------------------------------------------------------------------------
__global__ void wkv_kernel(const float* __restrict__ kbuf,
                           const float* __restrict__ rbuf,
                           const float* __restrict__ td,
                           const float* __restrict__ tf,
                           __nv_bfloat16* __restrict__ ohi,
                           __nv_bfloat16* __restrict__ olo)
{
    const int idx = blockIdx.x * blockDim.x + threadIdx.x;
    if (idx >= Bc * Cc) return;
    const int c = idx & (Cc - 1);
    const int b = idx >> 10;

    const float ew = __expf(-__expf(td[c]));
    const float eu = __expf(tf[c]);

    const float* kp = kbuf + (size_t)b * Tc * Cc + c;
    const float* rp = rbuf + (size_t)b * Tc * Cc + c;
    __nv_bfloat16* hp = ohi + (size_t)b * Tc * Cc + c;
    __nv_bfloat16* lp = olo + (size_t)b * Tc * Cc + c;

    float num = 0.f, den = 0.f;

    for (int t = 0; t < Tc; t += 4) {
        float kt[4], rt[4];
#pragma unroll
        for (int j = 0; j < 4; j++) {
            kt[j] = kp[(size_t)(t + j) * Cc];
            rt[j] = rp[(size_t)(t + j) * Cc];
        }
#pragma unroll
        for (int j = 0; j < 4; j++) {
            const float ek  = __expf(kt[j]);
            const float euk = eu * ek;
            const float y   = __fdividef(fmaf(euk, rt[j], num), den + euk);
            num = fmaf(ew, num, ek * rt[j]);
            den = fmaf(ew, den, ek);
            const float sg  = __fdividef(1.f, 1.f + __expf(-rt[j]));
            const float o   = sg * y;
            const __nv_bfloat16 h = __float2bfloat16(o);
            hp[(size_t)(t + j) * Cc] = h;
            lp[(size_t)(t + j) * Cc] = __float2bfloat16(o - __bfloat162float(h));
        }
    }
}

// ---------------------------------------------------------------------------
// Launch sequence (graph-capturable; default stream)
// ---------------------------------------------------------------------------
extern "C" void kernel_launch(void* const* d_in, const int* in_sizes, int n_in,
                              void* d_out, int out_size)
{
    const float* x  = (const float*)d_in[0];
    const float* Wk = (const float*)d_in[1];
    const float* Wr = (const float*)d_in[2];
    const float* Wo = (const float*)d_in[3];
    const float* td = (const float*)d_in[4];
    const float* tf = (const float*)d_in[5];
    float* out = (float*)d_out;

    __nv_bfloat16 *xhi, *xlo, *ohi, *olo;
    __nv_bfloat16 *wkhi, *wklo, *wrhi, *wrlo, *wohi, *wolo;
    float *pk, *pr;
    cudaGetSymbolAddress((void**)&xhi,  g_xhi);
    cudaGetSymbolAddress((void**)&xlo,  g_xlo);
    cudaGetSymbolAddress((void**)&ohi,  g_ohi);
    cudaGetSymbolAddress((void**)&olo,  g_olo);
    cudaGetSymbolAddress((void**)&pk,   g_k);
    cudaGetSymbolAddress((void**)&pr,   g_r);
    cudaGetSymbolAddress((void**)&wkhi, g_wkhi);
    cudaGetSymbolAddress((void**)&wklo, g_wklo);
    cudaGetSymbolAddress((void**)&wrhi, g_wrhi);
    cudaGetSymbolAddress((void**)&wrlo, g_wrlo);
    cudaGetSymbolAddress((void**)&wohi, g_wohi);
    cudaGetSymbolAddress((void**)&wolo, g_wolo);

    cudaFuncSetAttribute(gemm_hmma, cudaFuncAttributeMaxDynamicSharedMemorySize,
                         GEMM_SMEM);

    // fp32 -> split bf16
    const int nx4 = (Mc * Kc) / 4;
    const int nw4 = (Cc * Kc) / 4;
    split_kernel<<<nx4 / 256, 256>>>(x,  xhi,  xlo,  nx4);
    split_kernel<<<nw4 / 256, 256>>>(Wk, wkhi, wklo, nw4);
    split_kernel<<<nw4 / 256, 256>>>(Wr, wrhi, wrlo, nw4);
    split_kernel<<<nw4 / 256, 256>>>(Wo, wohi, wolo, nw4);

    // k = x*Wk^T ; r = x*Wr^T  (z fused)
    dim3 grid_kr(Cc / 128, Mc / 128, 2);
    gemm_hmma<<<grid_kr, 256, GEMM_SMEM>>>(xhi, xlo, wkhi, wklo, wrhi, wrlo,
                                           pk, pr);

    // o = sigmoid(r) * wkv(...)  -> split bf16
    wkv_kernel<<<(Bc * Cc) / 256, 256>>>(pk, pr, td, tf, ohi, olo);

    // out = o * Wo^T
    dim3 grid_o(Cc / 128, Mc / 128, 1);
    gemm_hmma<<<grid_o, 256, GEMM_SMEM>>>(ohi, olo, wohi, wolo, wohi, wolo,
                                          out, out);
}

// round 5
// speedup vs baseline: 3.3922x; 1.3341x over previous
#include <cuda_runtime.h>
#include <cuda_fp16.h>
#include <cstdint>
#include <cstddef>

// Problem shape (fixed)
#define Bc 16
#define Tc 1024
#define Cc 1024
#define Kc 1024
#define Mc (Bc * Tc)   // 16384

// ---------------------------------------------------------------------------
// Scratch (__device__ globals; no cudaMalloc allowed)
// ---------------------------------------------------------------------------
__device__ __half g_xh [(size_t)Mc * Kc];     // x as fp16
__device__ __half g_of [(size_t)Mc * Kc];     // gated wkv output as fp16
__device__ float  g_k  [(size_t)Mc * Cc];
__device__ float  g_r  [(size_t)Mc * Cc];
__device__ __half g_wkhi[Cc * Kc], g_wklo[Cc * Kc];
__device__ __half g_wrhi[Cc * Kc], g_wrlo[Cc * Kc];
__device__ __half g_wohi[Cc * Kc], g_wolo[Cc * Kc];

// ---------------------------------------------------------------------------
// Base-ISA PTX helpers (compile for plain .target sm_103)
// ---------------------------------------------------------------------------
__device__ __forceinline__ uint32_t smem_u32(const void* p) {
    uint32_t a;
    asm("{ .reg .u64 t; cvta.to.shared.u64 t, %1; cvt.u32.u64 %0, t; }"
        : "=r"(a) : "l"(p));
    return a;
}
__device__ __forceinline__ void cp_async16(uint32_t dst, const void* src) {
    asm volatile("cp.async.cg.shared.global [%0], [%1], 16;"
                 :: "r"(dst), "l"(src));
}
__device__ __forceinline__ void cp_commit() {
    asm volatile("cp.async.commit_group;");
}
__device__ __forceinline__ void cp_wait1() {
    asm volatile("cp.async.wait_group 1;" ::: "memory");
}
__device__ __forceinline__ void cp_wait0() {
    asm volatile("cp.async.wait_group 0;" ::: "memory");
}
__device__ __forceinline__ void ldm_x4(uint32_t* r, uint32_t addr) {
    asm volatile("ldmatrix.sync.aligned.m8n8.x4.shared.b16 {%0,%1,%2,%3}, [%4];"
                 : "=r"(r[0]), "=r"(r[1]), "=r"(r[2]), "=r"(r[3]) : "r"(addr));
}
__device__ __forceinline__ void mma_fp16(float* d, const uint32_t* a,
                                         const uint32_t* b) {
    asm volatile(
        "mma.sync.aligned.m16n8k16.row.col.f32.f16.f16.f32 "
        "{%0,%1,%2,%3}, {%4,%5,%6,%7}, {%8,%9}, {%0,%1,%2,%3};"
        : "+f"(d[0]), "+f"(d[1]), "+f"(d[2]), "+f"(d[3])
        : "r"(a[0]), "r"(a[1]), "r"(a[2]), "r"(a[3]), "r"(b[0]), "r"(b[1]));
}

// ---------------------------------------------------------------------------
// fp32 -> fp16 convert (activations), vectorized
// ---------------------------------------------------------------------------
__global__ void cvt_kernel(const float* __restrict__ src,
                           __half* __restrict__ dst, int n4)
{
    int i = blockIdx.x * blockDim.x + threadIdx.x;
    if (i >= n4) return;
    float4 v = reinterpret_cast<const float4*>(src)[i];
    __half2 h0 = __floats2half2_rn(v.x, v.y);
    __half2 h1 = __floats2half2_rn(v.z, v.w);
    reinterpret_cast<__half2*>(dst)[2 * i]     = h0;
    reinterpret_cast<__half2*>(dst)[2 * i + 1] = h1;
}

// ---------------------------------------------------------------------------
// fp32 -> (fp16 hi, fp16 lo) split (weights); lo may be subnormal fp16 — OK
// ---------------------------------------------------------------------------
__global__ void split_kernel(const float* __restrict__ src,
                             __half* __restrict__ hi,
                             __half* __restrict__ lo, int n4)
{
    int i = blockIdx.x * blockDim.x + threadIdx.x;
    if (i >= n4) return;
    float4 v = reinterpret_cast<const float4*>(src)[i];
    float vv[4] = {v.x, v.y, v.z, v.w};
    __half h[4], l[4];
#pragma unroll
    for (int j = 0; j < 4; j++) {
        h[j] = __float2half(vv[j]);
        l[j] = __float2half(vv[j] - __half2float(h[j]));
    }
    __half2 h0; h0.x = h[0]; h0.y = h[1];
    __half2 h1; h1.x = h[2]; h1.y = h[3];
    __half2 l0; l0.x = l[0]; l0.y = l[1];
    __half2 l1; l1.x = l[2]; l1.y = l[3];
    reinterpret_cast<__half2*>(hi)[2 * i]     = h0;
    reinterpret_cast<__half2*>(hi)[2 * i + 1] = h1;
    reinterpret_cast<__half2*>(lo)[2 * i]     = l0;
    reinterpret_cast<__half2*>(lo)[2 * i + 1] = l1;
}

// ---------------------------------------------------------------------------
// HMMA fp16 2-product NT GEMM: C[M,N] = A[M,K] * (Bhi + Blo)[N,K]^T
// A single fp16, B split. CTA tile 128x128, K-chunk 64 (128B swizzled rows),
// 8 warps (4m x 2n -> warp tile 32x64), 3-stage cp.async pipeline.
// blockIdx.z selects (B0,C0)/(B1,C1) so k and r GEMMs share one launch.
// ---------------------------------------------------------------------------
#define BK 64
#define TILE_B 16384                 // 128 rows * 128 bytes
#define STAGE_B (3 * TILE_B)         // A, Bhi, Blo
#define NSTAGE 3
#define GEMM_SMEM (NSTAGE * STAGE_B) // 147456 B
#define NCHUNK (Kc / BK)             // 16

__global__ __launch_bounds__(256)
void gemm_hmma(const __half* __restrict__ A,
               const __half* __restrict__ B0hi,
               const __half* __restrict__ B0lo,
               const __half* __restrict__ B1hi,
               const __half* __restrict__ B1lo,
               float* __restrict__ C0, float* __restrict__ C1)
{
    extern __shared__ char smem_raw[];
    const uint32_t sbase = smem_u32(smem_raw);

    const int tid  = threadIdx.x;
    const int wid  = tid >> 5;
    const int lane = tid & 31;

    const __half* Bhi = blockIdx.z ? B1hi : B0hi;
    const __half* Blo = blockIdx.z ? B1lo : B0lo;
    float* Cmat       = blockIdx.z ? C1   : C0;

    const int m0 = blockIdx.y * 128;
    const int n0 = blockIdx.x * 128;

    // ---- cp.async segment mapping: 3 tiles x 128 rows x 8 segs = 3072 ------
    const __half* srcs[3] = {
        A   + (size_t)m0 * Kc,
        Bhi + (size_t)n0 * Kc,
        Blo + (size_t)n0 * Kc
    };
    const __half* gsrc[12];
    uint32_t sdst[12];
#pragma unroll
    for (int i = 0; i < 12; i++) {
        const int sid = i * 256 + tid;
        const int mat = sid >> 10;
        const int row = (sid >> 3) & 127;
        const int s   = sid & 7;
        gsrc[i] = srcs[mat] + (size_t)row * Kc + s * 8;
        sdst[i] = mat * TILE_B + row * 128 + ((s ^ (row & 7)) << 4);
    }

    // ---- warp tiling -------------------------------------------------------
    const int wm = (wid & 3) * 32;
    const int wn = (wid >> 2) * 64;

    float acc[2][8][4];
#pragma unroll
    for (int mi = 0; mi < 2; mi++)
#pragma unroll
        for (int ni = 0; ni < 8; ni++)
#pragma unroll
            for (int j = 0; j < 4; j++) acc[mi][ni][j] = 0.f;

    const int a_row = wm + (lane & 15);
    const int a_ks  = lane >> 4;
    const int b_row = wn + (lane & 7) + ((lane >> 4) << 3);
    const int b_ks  = (lane >> 3) & 1;

    // ---- prologue: issue chunks 0 and 1 ------------------------------------
#pragma unroll
    for (int i = 0; i < 12; i++)
        cp_async16(sbase + 0 * STAGE_B + sdst[i], gsrc[i]);
    cp_commit();
#pragma unroll
    for (int i = 0; i < 12; i++)
        cp_async16(sbase + 1 * STAGE_B + sdst[i], gsrc[i] + BK);
    cp_commit();

    int stage_c = 0;      // stage holding chunk c
    for (int c = 0; c < NCHUNK; ++c) {
        if (c < NCHUNK - 1) cp_wait1(); else cp_wait0();
        __syncthreads();

        if (c + 2 < NCHUNK) {
            const int ns = (stage_c + 2) % NSTAGE;
            const uint32_t nbuf = sbase + ns * STAGE_B;
            const int koff = (c + 2) * BK;
#pragma unroll
            for (int i = 0; i < 12; i++)
                cp_async16(nbuf + sdst[i], gsrc[i] + koff);
            cp_commit();
        }

        const uint32_t buf = sbase + stage_c * STAGE_B;
#pragma unroll
        for (int ks = 0; ks < 4; ks++) {
            uint32_t af[2][4];
#pragma unroll
            for (int mi = 0; mi < 2; mi++) {
                const int row = a_row + mi * 16;
                const int sg  = (ks * 2 + a_ks) ^ (row & 7);
                ldm_x4(af[mi], buf + 0 * TILE_B + row * 128 + (sg << 4));
            }
            uint32_t bfh[4][4], bfl[4][4];
#pragma unroll
            for (int ni = 0; ni < 4; ni++) {
                const int row = b_row + ni * 16;
                const int sg  = (ks * 2 + b_ks) ^ (row & 7);
                const uint32_t off = row * 128 + (sg << 4);
                ldm_x4(bfh[ni], buf + 1 * TILE_B + off);
                ldm_x4(bfl[ni], buf + 2 * TILE_B + off);
            }
#pragma unroll
            for (int mi = 0; mi < 2; mi++)
#pragma unroll
                for (int ni = 0; ni < 4; ni++) {
                    mma_fp16(acc[mi][2 * ni],     af[mi], &bfh[ni][0]);
                    mma_fp16(acc[mi][2 * ni + 1], af[mi], &bfh[ni][2]);
                    mma_fp16(acc[mi][2 * ni],     af[mi], &bfl[ni][0]);
                    mma_fp16(acc[mi][2 * ni + 1], af[mi], &bfl[ni][2]);
                }
        }
        stage_c = (stage_c + 1) % NSTAGE;
    }

    // ---- epilogue ----------------------------------------------------------
    const int er = lane >> 2;
    const int ec = (lane & 3) * 2;
#pragma unroll
    for (int mi = 0; mi < 2; mi++) {
        const int mb = m0 + wm + mi * 16;
#pragma unroll
        for (int ni = 0; ni < 8; ni++) {
            const int nb = n0 + wn + ni * 8;
            float2 v0 = make_float2(acc[mi][ni][0], acc[mi][ni][1]);
            float2 v1 = make_float2(acc[mi][ni][2], acc[mi][ni][3]);
            *reinterpret_cast<float2*>(Cmat + (size_t)(mb + er) * Cc + nb + ec) = v0;
            *reinterpret_cast<float2*>(Cmat + (size_t)(mb + 8 + er) * Cc + nb + ec) = v1;
        }
    }
}

// ---------------------------------------------------------------------------
// WKV scan (direct form; safe: decay<1, |k| small). o = sigmoid(r)*y -> fp16.
// ---------------------------------------------------------------------------
__global__ void wkv_kernel(const float* __restrict__ kbuf,
                           const float* __restrict__ rbuf,
                           const float* __restrict__ td,
                           const float* __restrict__ tf,
                           __half* __restrict__ obuf)
{
    const int idx = blockIdx.x * blockDim.x + threadIdx.x;
    if (idx >= Bc * Cc) return;
    const int c = idx & (Cc - 1);
    const int b = idx >> 10;

    const float ew = __expf(-__expf(td[c]));
    const float eu = __expf(tf[c]);

    const float* kp = kbuf + (size_t)b * Tc * Cc + c;
    const float* rp = rbuf + (size_t)b * Tc * Cc + c;
    __half*      op = obuf + (size_t)b * Tc * Cc + c;

    float num = 0.f, den = 0.f;

    for (int t = 0; t < Tc; t += 4) {
        float kt[4], rt[4];
#pragma unroll
        for (int j = 0; j < 4; j++) {
            kt[j] = kp[(size_t)(t + j) * Cc];
            rt[j] = rp[(size_t)(t + j) * Cc];
        }
#pragma unroll
        for (int j = 0; j < 4; j++) {
            const float ek  = __expf(kt[j]);
            const float euk = eu * ek;
            const float y   = __fdividef(fmaf(euk, rt[j], num), den + euk);
            num = fmaf(ew, num, ek * rt[j]);
            den = fmaf(ew, den, ek);
            const float sg  = __fdividef(1.f, 1.f + __expf(-rt[j]));
            op[(size_t)(t + j) * Cc] = __float2half(sg * y);
        }
    }
}

// ---------------------------------------------------------------------------
// Launch sequence (graph-capturable; default stream)
// ---------------------------------------------------------------------------
extern "C" void kernel_launch(void* const* d_in, const int* in_sizes, int n_in,
                              void* d_out, int out_size)
{
    const float* x  = (const float*)d_in[0];
    const float* Wk = (const float*)d_in[1];
    const float* Wr = (const float*)d_in[2];
    const float* Wo = (const float*)d_in[3];
    const float* td = (const float*)d_in[4];
    const float* tf = (const float*)d_in[5];
    float* out = (float*)d_out;

    __half *xh, *of;
    __half *wkhi, *wklo, *wrhi, *wrlo, *wohi, *wolo;
    float *pk, *pr;
    cudaGetSymbolAddress((void**)&xh,   g_xh);
    cudaGetSymbolAddress((void**)&of,   g_of);
    cudaGetSymbolAddress((void**)&pk,   g_k);
    cudaGetSymbolAddress((void**)&pr,   g_r);
    cudaGetSymbolAddress((void**)&wkhi, g_wkhi);
    cudaGetSymbolAddress((void**)&wklo, g_wklo);
    cudaGetSymbolAddress((void**)&wrhi, g_wrhi);
    cudaGetSymbolAddress((void**)&wrlo, g_wrlo);
    cudaGetSymbolAddress((void**)&wohi, g_wohi);
    cudaGetSymbolAddress((void**)&wolo, g_wolo);

    cudaFuncSetAttribute(gemm_hmma, cudaFuncAttributeMaxDynamicSharedMemorySize,
                         GEMM_SMEM);

    const int nx4 = (Mc * Kc) / 4;
    const int nw4 = (Cc * Kc) / 4;
    cvt_kernel<<<nx4 / 256, 256>>>(x, xh, nx4);
    split_kernel<<<nw4 / 256, 256>>>(Wk, wkhi, wklo, nw4);
    split_kernel<<<nw4 / 256, 256>>>(Wr, wrhi, wrlo, nw4);
    split_kernel<<<nw4 / 256, 256>>>(Wo, wohi, wolo, nw4);

    // k = x*Wk^T ; r = x*Wr^T  (z fused)
    dim3 grid_kr(Cc / 128, Mc / 128, 2);
    gemm_hmma<<<grid_kr, 256, GEMM_SMEM>>>(xh, wkhi, wklo, wrhi, wrlo, pk, pr);

    // o = sigmoid(r) * wkv(...) -> fp16
    wkv_kernel<<<(Bc * Cc) / 128, 128>>>(pk, pr, td, tf, of);

    // out = o * Wo^T
    dim3 grid_o(Cc / 128, Mc / 128, 1);
    gemm_hmma<<<grid_o, 256, GEMM_SMEM>>>(of, wohi, wolo, wohi, wolo, out, out);
}

// round 6
// speedup vs baseline: 4.2336x; 1.2481x over previous
#include <cuda_runtime.h>
#include <cuda_fp16.h>
#include <cstdint>
#include <cstddef>

// Problem shape (fixed)
#define Bc 16
#define Tc 1024
#define Cc 1024
#define Kc 1024
#define Mc (Bc * Tc)   // 16384

// ---------------------------------------------------------------------------
// Scratch (__device__ globals; no cudaMalloc allowed)
// ---------------------------------------------------------------------------
__device__ __half g_xh [(size_t)Mc * Kc];     // x as fp16
__device__ __half g_of [(size_t)Mc * Kc];     // gated wkv output as fp16
__device__ float  g_k  [(size_t)Mc * Cc];
__device__ float  g_r  [(size_t)Mc * Cc];
__device__ __half g_wkhi[Cc * Kc], g_wklo[Cc * Kc];   // Wk split (2-term)
__device__ __half g_wrh [Cc * Kc];                     // Wr single fp16
__device__ __half g_woh [Cc * Kc];                     // Wo single fp16

// ---------------------------------------------------------------------------
// Base-ISA PTX helpers (compile for plain .target sm_103)
// ---------------------------------------------------------------------------
__device__ __forceinline__ uint32_t smem_u32(const void* p) {
    uint32_t a;
    asm("{ .reg .u64 t; cvta.to.shared.u64 t, %1; cvt.u32.u64 %0, t; }"
        : "=r"(a) : "l"(p));
    return a;
}
__device__ __forceinline__ void cp_async16(uint32_t dst, const void* src) {
    asm volatile("cp.async.cg.shared.global [%0], [%1], 16;"
                 :: "r"(dst), "l"(src));
}
__device__ __forceinline__ void cp_commit() {
    asm volatile("cp.async.commit_group;");
}
__device__ __forceinline__ void cp_wait1() {
    asm volatile("cp.async.wait_group 1;" ::: "memory");
}
__device__ __forceinline__ void cp_wait0() {
    asm volatile("cp.async.wait_group 0;" ::: "memory");
}
__device__ __forceinline__ void ldm_x4(uint32_t* r, uint32_t addr) {
    asm volatile("ldmatrix.sync.aligned.m8n8.x4.shared.b16 {%0,%1,%2,%3}, [%4];"
                 : "=r"(r[0]), "=r"(r[1]), "=r"(r[2]), "=r"(r[3]) : "r"(addr));
}
__device__ __forceinline__ void mma_fp16(float* d, const uint32_t* a,
                                         const uint32_t* b) {
    asm volatile(
        "mma.sync.aligned.m16n8k16.row.col.f32.f16.f16.f32 "
        "{%0,%1,%2,%3}, {%4,%5,%6,%7}, {%8,%9}, {%0,%1,%2,%3};"
        : "+f"(d[0]), "+f"(d[1]), "+f"(d[2]), "+f"(d[3])
        : "r"(a[0]), "r"(a[1]), "r"(a[2]), "r"(a[3]), "r"(b[0]), "r"(b[1]));
}

// ---------------------------------------------------------------------------
// fp32 -> fp16 convert, vectorized
// ---------------------------------------------------------------------------
__global__ void cvt_kernel(const float* __restrict__ src,
                           __half* __restrict__ dst, int n4)
{
    int i = blockIdx.x * blockDim.x + threadIdx.x;
    if (i >= n4) return;
    float4 v = reinterpret_cast<const float4*>(src)[i];
    reinterpret_cast<__half2*>(dst)[2 * i]     = __floats2half2_rn(v.x, v.y);
    reinterpret_cast<__half2*>(dst)[2 * i + 1] = __floats2half2_rn(v.z, v.w);
}

// ---------------------------------------------------------------------------
// fp32 -> (fp16 hi, fp16 lo) split (Wk only)
// ---------------------------------------------------------------------------
__global__ void split_kernel(const float* __restrict__ src,
                             __half* __restrict__ hi,
                             __half* __restrict__ lo, int n4)
{
    int i = blockIdx.x * blockDim.x + threadIdx.x;
    if (i >= n4) return;
    float4 v = reinterpret_cast<const float4*>(src)[i];
    float vv[4] = {v.x, v.y, v.z, v.w};
    __half h[4], l[4];
#pragma unroll
    for (int j = 0; j < 4; j++) {
        h[j] = __float2half(vv[j]);
        l[j] = __float2half(vv[j] - __half2float(h[j]));
    }
    __half2 h0; h0.x = h[0]; h0.y = h[1];
    __half2 h1; h1.x = h[2]; h1.y = h[3];
    __half2 l0; l0.x = l[0]; l0.y = l[1];
    __half2 l1; l1.x = l[2]; l1.y = l[3];
    reinterpret_cast<__half2*>(hi)[2 * i]     = h0;
    reinterpret_cast<__half2*>(hi)[2 * i + 1] = h1;
    reinterpret_cast<__half2*>(lo)[2 * i]     = l0;
    reinterpret_cast<__half2*>(lo)[2 * i + 1] = l1;
}

// ---------------------------------------------------------------------------
// HMMA NT GEMM: C[M,1024] = A[M,K] * B[N,K]^T with optional 2-term B split.
// CTA tile 128(M) x 256(N), K-chunk 64 (128B swizzled rows), 8 warps in a
// 2(m) x 4(n) grid -> warp tile 64x64. 2-stage cp.async double buffer.
// sel = blockIdx.z + selbase:  sel==0 -> (Bh2+Bl2, C2, 2-term)
//                              sel!=0 -> (Bh1, C1, 1-term)
// ---------------------------------------------------------------------------
#define BK 64
#define BH_OFF  16384               // A tile 128*128B
#define BLO_OFF 49152               // Bhi tile 256*128B
#define STAGE_B 81920               // A + Bhi + Blo
#define GEMM_SMEM (2 * STAGE_B)     // 163840
#define NCHUNK (Kc / BK)            // 16

__global__ __launch_bounds__(256, 1)
void gemm_hmma(const __half* __restrict__ A,
               const __half* __restrict__ Bh2,
               const __half* __restrict__ Bl2,
               float* __restrict__ C2,
               const __half* __restrict__ Bh1,
               float* __restrict__ C1,
               int selbase)
{
    extern __shared__ char smem_raw[];
    const uint32_t sbase = smem_u32(smem_raw);

    const int tid  = threadIdx.x;
    const int wid  = tid >> 5;
    const int lane = tid & 31;

    const int sel = blockIdx.z + selbase;
    const bool two = (sel == 0);
    const __half* Bh = two ? Bh2 : Bh1;
    const __half* Bl = Bl2;
    float* Cmat      = two ? C2  : C1;

    const int m0 = blockIdx.y * 128;
    const int n0 = blockIdx.x * 256;

    const __half* Ap  = A  + (size_t)m0 * Kc;
    const __half* Bhp = Bh + (size_t)n0 * Kc;
    const __half* Blp = two ? (Bl + (size_t)n0 * Kc) : Bhp;

    // ---- cp.async segment maps ---------------------------------------------
    uint32_t sdstA[4], goffA[4];
#pragma unroll
    for (int i = 0; i < 4; i++) {
        const int sid = i * 256 + tid;        // 0..1023
        const int row = sid >> 3;             // 0..127
        const int s   = sid & 7;
        sdstA[i] = row * 128 + ((s ^ (row & 7)) << 4);
        goffA[i] = row * Kc + s * 8;
    }
    uint32_t sdstB[8], goffB[8];
#pragma unroll
    for (int j = 0; j < 8; j++) {
        const int sid = j * 256 + tid;        // 0..2047
        const int row = sid >> 3;             // 0..255
        const int s   = sid & 7;
        sdstB[j] = BH_OFF + row * 128 + ((s ^ (row & 7)) << 4);
        goffB[j] = row * Kc + s * 8;
    }

    // ---- warp tiling -------------------------------------------------------
    const int wm = (wid & 1) * 64;
    const int wn = (wid >> 1) * 64;

    float acc[4][8][4];
#pragma unroll
    for (int mi = 0; mi < 4; mi++)
#pragma unroll
        for (int ni = 0; ni < 8; ni++)
#pragma unroll
            for (int j = 0; j < 4; j++) acc[mi][ni][j] = 0.f;

    const int a_row = wm + (lane & 15);
    const int a_ks  = lane >> 4;
    const int b_row = wn + (lane & 7) + ((lane >> 4) << 3);
    const int b_ks  = (lane >> 3) & 1;

    // ---- issue helper (macro to keep regs flat) ----------------------------
#define ISSUE_CHUNK(chunk, stagebuf) do {                                      \
    const int _ko = (chunk) * BK;                                              \
    _Pragma("unroll")                                                          \
    for (int i = 0; i < 4; i++)                                                \
        cp_async16((stagebuf) + sdstA[i], Ap + goffA[i] + _ko);                \
    _Pragma("unroll")                                                          \
    for (int j = 0; j < 8; j++)                                                \
        cp_async16((stagebuf) + sdstB[j], Bhp + goffB[j] + _ko);               \
    if (two) {                                                                 \
        _Pragma("unroll")                                                      \
        for (int j = 0; j < 8; j++)                                            \
            cp_async16((stagebuf) + sdstB[j] + (BLO_OFF - BH_OFF),             \
                       Blp + goffB[j] + _ko);                                  \
    }                                                                          \
    cp_commit();                                                               \
} while (0)

    ISSUE_CHUNK(0, sbase);
    ISSUE_CHUNK(1, sbase + STAGE_B);

    for (int c = 0; c < NCHUNK; ++c) {
        if (c + 1 < NCHUNK) cp_wait1(); else cp_wait0();
        __syncthreads();

        const uint32_t buf = sbase + (c & 1) * STAGE_B;
#pragma unroll
        for (int ks = 0; ks < 4; ks++) {
            uint32_t af[4][4];
#pragma unroll
            for (int mi = 0; mi < 4; mi++) {
                const int row = a_row + mi * 16;
                const int sg  = (ks * 2 + a_ks) ^ (row & 7);
                ldm_x4(af[mi], buf + row * 128 + (sg << 4));
            }
#pragma unroll
            for (int ni = 0; ni < 4; ni++) {
                const int row = b_row + ni * 16;
                const int sg  = (ks * 2 + b_ks) ^ (row & 7);
                const uint32_t off = row * 128 + (sg << 4);
                uint32_t bh[4];
                ldm_x4(bh, buf + BH_OFF + off);
#pragma unroll
                for (int mi = 0; mi < 4; mi++) {
                    mma_fp16(acc[mi][2 * ni],     af[mi], bh);
                    mma_fp16(acc[mi][2 * ni + 1], af[mi], bh + 2);
                }
                if (two) {
                    uint32_t bl[4];
                    ldm_x4(bl, buf + BLO_OFF + off);
#pragma unroll
                    for (int mi = 0; mi < 4; mi++) {
                        mma_fp16(acc[mi][2 * ni],     af[mi], bl);
                        mma_fp16(acc[mi][2 * ni + 1], af[mi], bl + 2);
                    }
                }
            }
        }
        __syncthreads();
        if (c + 2 < NCHUNK) {
            ISSUE_CHUNK(c + 2, buf);
        }
    }
#undef ISSUE_CHUNK

    // ---- epilogue ----------------------------------------------------------
    const int er = lane >> 2;
    const int ec = (lane & 3) * 2;
#pragma unroll
    for (int mi = 0; mi < 4; mi++) {
        const int mb = m0 + wm + mi * 16;
#pragma unroll
        for (int ni = 0; ni < 8; ni++) {
            const int nb = n0 + wn + ni * 8;
            float2 v0 = make_float2(acc[mi][ni][0], acc[mi][ni][1]);
            float2 v1 = make_float2(acc[mi][ni][2], acc[mi][ni][3]);
            *reinterpret_cast<float2*>(Cmat + (size_t)(mb + er) * Cc + nb + ec) = v0;
            *reinterpret_cast<float2*>(Cmat + (size_t)(mb + 8 + er) * Cc + nb + ec) = v1;
        }
    }
}

// ---------------------------------------------------------------------------
// WKV scan (direct form; safe: decay<1, |k| small). o = sigmoid(r)*y -> fp16.
// ---------------------------------------------------------------------------
__global__ void wkv_kernel(const float* __restrict__ kbuf,
                           const float* __restrict__ rbuf,
                           const float* __restrict__ td,
                           const float* __restrict__ tf,
                           __half* __restrict__ obuf)
{
    const int idx = blockIdx.x * blockDim.x + threadIdx.x;
    if (idx >= Bc * Cc) return;
    const int c = idx & (Cc - 1);
    const int b = idx >> 10;

    const float ew = __expf(-__expf(td[c]));
    const float eu = __expf(tf[c]);

    const float* kp = kbuf + (size_t)b * Tc * Cc + c;
    const float* rp = rbuf + (size_t)b * Tc * Cc + c;
    __half*      op = obuf + (size_t)b * Tc * Cc + c;

    float num = 0.f, den = 0.f;

    for (int t = 0; t < Tc; t += 4) {
        float kt[4], rt[4];
#pragma unroll
        for (int j = 0; j < 4; j++) {
            kt[j] = kp[(size_t)(t + j) * Cc];
            rt[j] = rp[(size_t)(t + j) * Cc];
        }
#pragma unroll
        for (int j = 0; j < 4; j++) {
            const float ek  = __expf(kt[j]);
            const float euk = eu * ek;
            const float y   = __fdividef(fmaf(euk, rt[j], num), den + euk);
            num = fmaf(ew, num, ek * rt[j]);
            den = fmaf(ew, den, ek);
            const float sg  = __fdividef(1.f, 1.f + __expf(-rt[j]));
            op[(size_t)(t + j) * Cc] = __float2half(sg * y);
        }
    }
}

// ---------------------------------------------------------------------------
// Launch sequence (graph-capturable; default stream)
// ---------------------------------------------------------------------------
extern "C" void kernel_launch(void* const* d_in, const int* in_sizes, int n_in,
                              void* d_out, int out_size)
{
    const float* x  = (const float*)d_in[0];
    const float* Wk = (const float*)d_in[1];
    const float* Wr = (const float*)d_in[2];
    const float* Wo = (const float*)d_in[3];
    const float* td = (const float*)d_in[4];
    const float* tf = (const float*)d_in[5];
    float* out = (float*)d_out;

    __half *xh, *of, *wkhi, *wklo, *wrh, *woh;
    float *pk, *pr;
    cudaGetSymbolAddress((void**)&xh,   g_xh);
    cudaGetSymbolAddress((void**)&of,   g_of);
    cudaGetSymbolAddress((void**)&pk,   g_k);
    cudaGetSymbolAddress((void**)&pr,   g_r);
    cudaGetSymbolAddress((void**)&wkhi, g_wkhi);
    cudaGetSymbolAddress((void**)&wklo, g_wklo);
    cudaGetSymbolAddress((void**)&wrh,  g_wrh);
    cudaGetSymbolAddress((void**)&woh,  g_woh);

    cudaFuncSetAttribute(gemm_hmma, cudaFuncAttributeMaxDynamicSharedMemorySize,
                         GEMM_SMEM);

    const int nx4 = (Mc * Kc) / 4;
    const int nw4 = (Cc * Kc) / 4;
    cvt_kernel<<<nx4 / 256, 256>>>(x, xh, nx4);
    split_kernel<<<nw4 / 256, 256>>>(Wk, wkhi, wklo, nw4);
    cvt_kernel<<<nw4 / 256, 256>>>(Wr, wrh, nw4);
    cvt_kernel<<<nw4 / 256, 256>>>(Wo, woh, nw4);

    // z=0: k = x*Wk^T (2-term);  z=1: r = x*Wr^T (1-term)
    dim3 grid_kr(Cc / 256, Mc / 128, 2);
    gemm_hmma<<<grid_kr, 256, GEMM_SMEM>>>(xh, wkhi, wklo, pk, wrh, pr, 0);

    // o = sigmoid(r) * wkv(...) -> fp16
    wkv_kernel<<<(Bc * Cc) / 128, 128>>>(pk, pr, td, tf, of);

    // out = o * Wo^T (1-term)
    dim3 grid_o(Cc / 256, Mc / 128, 1);
    gemm_hmma<<<grid_o, 256, GEMM_SMEM>>>(of, nullptr, nullptr, nullptr, woh,
                                          out, 1);
}

// round 7
// speedup vs baseline: 5.6523x; 1.3351x over previous
#include <cuda_runtime.h>
#include <cuda_fp16.h>
#include <cstdint>
#include <cstddef>

// Problem shape (fixed)
#define Bc 16
#define Tc 1024
#define Cc 1024
#define Kc 1024
#define Mc (Bc * Tc)   // 16384
#define NSEG 16
#define SEGL (Tc / NSEG)   // 64
#define LANES (Bc * Cc)    // 16384

// ---------------------------------------------------------------------------
// Scratch (__device__ globals; no cudaMalloc allowed)
// ---------------------------------------------------------------------------
__device__ __half g_xh [(size_t)Mc * Kc];     // x as fp16
__device__ __half g_of [(size_t)Mc * Kc];     // gated wkv output as fp16
__device__ __half g_k  [(size_t)Mc * Cc];     // k as fp16
__device__ __half g_r  [(size_t)Mc * Cc];     // r as fp16
__device__ __half g_wkhi[Cc * Kc], g_wklo[Cc * Kc];   // Wk split (2-term)
__device__ __half g_wrh [Cc * Kc];                     // Wr single fp16
__device__ __half g_woh [Cc * Kc];                     // Wo single fp16
__device__ float  g_pn [NSEG * LANES];        // per-segment partial num
__device__ float  g_pd [NSEG * LANES];        // per-segment partial den

// ---------------------------------------------------------------------------
// Base-ISA PTX helpers (compile for plain .target sm_103)
// ---------------------------------------------------------------------------
__device__ __forceinline__ uint32_t smem_u32(const void* p) {
    uint32_t a;
    asm("{ .reg .u64 t; cvta.to.shared.u64 t, %1; cvt.u32.u64 %0, t; }"
        : "=r"(a) : "l"(p));
    return a;
}
__device__ __forceinline__ void cp_async16(uint32_t dst, const void* src) {
    asm volatile("cp.async.cg.shared.global [%0], [%1], 16;"
                 :: "r"(dst), "l"(src));
}
__device__ __forceinline__ void cp_commit() {
    asm volatile("cp.async.commit_group;");
}
__device__ __forceinline__ void cp_wait1() {
    asm volatile("cp.async.wait_group 1;" ::: "memory");
}
__device__ __forceinline__ void cp_wait0() {
    asm volatile("cp.async.wait_group 0;" ::: "memory");
}
__device__ __forceinline__ void ldm_x4(uint32_t* r, uint32_t addr) {
    asm volatile("ldmatrix.sync.aligned.m8n8.x4.shared.b16 {%0,%1,%2,%3}, [%4];"
                 : "=r"(r[0]), "=r"(r[1]), "=r"(r[2]), "=r"(r[3]) : "r"(addr));
}
__device__ __forceinline__ void mma_fp16(float* d, const uint32_t* a,
                                         const uint32_t* b) {
    asm volatile(
        "mma.sync.aligned.m16n8k16.row.col.f32.f16.f16.f32 "
        "{%0,%1,%2,%3}, {%4,%5,%6,%7}, {%8,%9}, {%0,%1,%2,%3};"
        : "+f"(d[0]), "+f"(d[1]), "+f"(d[2]), "+f"(d[3])
        : "r"(a[0]), "r"(a[1]), "r"(a[2]), "r"(a[3]), "r"(b[0]), "r"(b[1]));
}

// ---------------------------------------------------------------------------
// fp32 -> fp16 convert (x), vectorized
// ---------------------------------------------------------------------------
__global__ void cvt_kernel(const float* __restrict__ src,
                           __half* __restrict__ dst, int n4)
{
    int i = blockIdx.x * blockDim.x + threadIdx.x;
    if (i >= n4) return;
    float4 v = reinterpret_cast<const float4*>(src)[i];
    reinterpret_cast<__half2*>(dst)[2 * i]     = __floats2half2_rn(v.x, v.y);
    reinterpret_cast<__half2*>(dst)[2 * i + 1] = __floats2half2_rn(v.z, v.w);
}

// ---------------------------------------------------------------------------
// Fused weight prep: Wk -> (hi, lo) split; Wr, Wo -> fp16
// ---------------------------------------------------------------------------
__global__ void wcvt_kernel(const float* __restrict__ Wk,
                            const float* __restrict__ Wr,
                            const float* __restrict__ Wo,
                            __half* __restrict__ wkhi, __half* __restrict__ wklo,
                            __half* __restrict__ wrh,  __half* __restrict__ woh,
                            int n4)
{
    int i = blockIdx.x * blockDim.x + threadIdx.x;
    if (i >= n4) return;

    // Wk split
    {
        float4 v = reinterpret_cast<const float4*>(Wk)[i];
        float vv[4] = {v.x, v.y, v.z, v.w};
        __half h[4], l[4];
#pragma unroll
        for (int j = 0; j < 4; j++) {
            h[j] = __float2half(vv[j]);
            l[j] = __float2half(vv[j] - __half2float(h[j]));
        }
        __half2 h0; h0.x = h[0]; h0.y = h[1];
        __half2 h1; h1.x = h[2]; h1.y = h[3];
        __half2 l0; l0.x = l[0]; l0.y = l[1];
        __half2 l1; l1.x = l[2]; l1.y = l[3];
        reinterpret_cast<__half2*>(wkhi)[2 * i]     = h0;
        reinterpret_cast<__half2*>(wkhi)[2 * i + 1] = h1;
        reinterpret_cast<__half2*>(wklo)[2 * i]     = l0;
        reinterpret_cast<__half2*>(wklo)[2 * i + 1] = l1;
    }
    // Wr, Wo plain converts
    {
        float4 v = reinterpret_cast<const float4*>(Wr)[i];
        reinterpret_cast<__half2*>(wrh)[2 * i]     = __floats2half2_rn(v.x, v.y);
        reinterpret_cast<__half2*>(wrh)[2 * i + 1] = __floats2half2_rn(v.z, v.w);
    }
    {
        float4 v = reinterpret_cast<const float4*>(Wo)[i];
        reinterpret_cast<__half2*>(woh)[2 * i]     = __floats2half2_rn(v.x, v.y);
        reinterpret_cast<__half2*>(woh)[2 * i + 1] = __floats2half2_rn(v.z, v.w);
    }
}

// ---------------------------------------------------------------------------
// HMMA NT GEMM: C[M,1024] = A[M,K] * B[N,K]^T with optional 2-term B split.
// CTA tile 128(M) x 256(N), K-chunk 64, 8 warps (2m x 4n -> 64x64 warp tile),
// 2-stage cp.async pipeline. Output fp16 (half_out=1) or fp32.
// ---------------------------------------------------------------------------
#define BK 64
#define BH_OFF  16384               // A tile 128*128B
#define BLO_OFF 49152               // Bhi tile 256*128B
#define STAGE_B 81920               // A + Bhi + Blo
#define GEMM_SMEM (2 * STAGE_B)     // 163840
#define NCHUNK (Kc / BK)            // 16

__global__ __launch_bounds__(256, 1)
void gemm_hmma(const __half* __restrict__ A,
               const __half* __restrict__ Bh2,
               const __half* __restrict__ Bl2,
               void* __restrict__ C2,
               const __half* __restrict__ Bh1,
               void* __restrict__ C1,
               int selbase, int half_out)
{
    extern __shared__ char smem_raw[];
    const uint32_t sbase = smem_u32(smem_raw);

    const int tid  = threadIdx.x;
    const int wid  = tid >> 5;
    const int lane = tid & 31;

    const int sel = blockIdx.z + selbase;
    const bool two = (sel == 0);
    const __half* Bh = two ? Bh2 : Bh1;
    void* Cmat       = two ? C2  : C1;

    const int m0 = blockIdx.y * 128;
    const int n0 = blockIdx.x * 256;

    const __half* Ap  = A  + (size_t)m0 * Kc;
    const __half* Bhp = Bh + (size_t)n0 * Kc;
    const __half* Blp = two ? (Bl2 + (size_t)n0 * Kc) : Bhp;

    // ---- cp.async segment maps ---------------------------------------------
    uint32_t sdstA[4], goffA[4];
#pragma unroll
    for (int i = 0; i < 4; i++) {
        const int sid = i * 256 + tid;
        const int row = sid >> 3;
        const int s   = sid & 7;
        sdstA[i] = row * 128 + ((s ^ (row & 7)) << 4);
        goffA[i] = row * Kc + s * 8;
    }
    uint32_t sdstB[8], goffB[8];
#pragma unroll
    for (int j = 0; j < 8; j++) {
        const int sid = j * 256 + tid;
        const int row = sid >> 3;
        const int s   = sid & 7;
        sdstB[j] = BH_OFF + row * 128 + ((s ^ (row & 7)) << 4);
        goffB[j] = row * Kc + s * 8;
    }

    // ---- warp tiling -------------------------------------------------------
    const int wm = (wid & 1) * 64;
    const int wn = (wid >> 1) * 64;

    float acc[4][8][4];
#pragma unroll
    for (int mi = 0; mi < 4; mi++)
#pragma unroll
        for (int ni = 0; ni < 8; ni++)
#pragma unroll
            for (int j = 0; j < 4; j++) acc[mi][ni][j] = 0.f;

    const int a_row = wm + (lane & 15);
    const int a_ks  = lane >> 4;
    const int b_row = wn + (lane & 7) + ((lane >> 4) << 3);
    const int b_ks  = (lane >> 3) & 1;

#define ISSUE_CHUNK(chunk, stagebuf) do {                                      \
    const int _ko = (chunk) * BK;                                              \
    _Pragma("unroll")                                                          \
    for (int i = 0; i < 4; i++)                                                \
        cp_async16((stagebuf) + sdstA[i], Ap + goffA[i] + _ko);                \
    _Pragma("unroll")                                                          \
    for (int j = 0; j < 8; j++)                                                \
        cp_async16((stagebuf) + sdstB[j], Bhp + goffB[j] + _ko);               \
    if (two) {                                                                 \
        _Pragma("unroll")                                                      \
        for (int j = 0; j < 8; j++)                                            \
            cp_async16((stagebuf) + sdstB[j] + (BLO_OFF - BH_OFF),             \
                       Blp + goffB[j] + _ko);                                  \
    }                                                                          \
    cp_commit();                                                               \
} while (0)

    ISSUE_CHUNK(0, sbase);
    ISSUE_CHUNK(1, sbase + STAGE_B);

    for (int c = 0; c < NCHUNK; ++c) {
        if (c + 1 < NCHUNK) cp_wait1(); else cp_wait0();
        __syncthreads();

        const uint32_t buf = sbase + (c & 1) * STAGE_B;
#pragma unroll
        for (int ks = 0; ks < 4; ks++) {
            uint32_t af[4][4];
#pragma unroll
            for (int mi = 0; mi < 4; mi++) {
                const int row = a_row + mi * 16;
                const int sg  = (ks * 2 + a_ks) ^ (row & 7);
                ldm_x4(af[mi], buf + row * 128 + (sg << 4));
            }
#pragma unroll
            for (int ni = 0; ni < 4; ni++) {
                const int row = b_row + ni * 16;
                const int sg  = (ks * 2 + b_ks) ^ (row & 7);
                const uint32_t off = row * 128 + (sg << 4);
                uint32_t bh[4];
                ldm_x4(bh, buf + BH_OFF + off);
#pragma unroll
                for (int mi = 0; mi < 4; mi++) {
                    mma_fp16(acc[mi][2 * ni],     af[mi], bh);
                    mma_fp16(acc[mi][2 * ni + 1], af[mi], bh + 2);
                }
                if (two) {
                    uint32_t bl[4];
                    ldm_x4(bl, buf + BLO_OFF + off);
#pragma unroll
                    for (int mi = 0; mi < 4; mi++) {
                        mma_fp16(acc[mi][2 * ni],     af[mi], bl);
                        mma_fp16(acc[mi][2 * ni + 1], af[mi], bl + 2);
                    }
                }
            }
        }
        __syncthreads();
        if (c + 2 < NCHUNK) {
            ISSUE_CHUNK(c + 2, buf);
        }
    }
#undef ISSUE_CHUNK

    // ---- epilogue ----------------------------------------------------------
    const int er = lane >> 2;
    const int ec = (lane & 3) * 2;
    if (half_out) {
        __half* C = (__half*)Cmat;
#pragma unroll
        for (int mi = 0; mi < 4; mi++) {
            const int mb = m0 + wm + mi * 16;
#pragma unroll
            for (int ni = 0; ni < 8; ni++) {
                const int nb = n0 + wn + ni * 8;
                *reinterpret_cast<__half2*>(C + (size_t)(mb + er) * Cc + nb + ec) =
                    __floats2half2_rn(acc[mi][ni][0], acc[mi][ni][1]);
                *reinterpret_cast<__half2*>(C + (size_t)(mb + 8 + er) * Cc + nb + ec) =
                    __floats2half2_rn(acc[mi][ni][2], acc[mi][ni][3]);
            }
        }
    } else {
        float* C = (float*)Cmat;
#pragma unroll
        for (int mi = 0; mi < 4; mi++) {
            const int mb = m0 + wm + mi * 16;
#pragma unroll
            for (int ni = 0; ni < 8; ni++) {
                const int nb = n0 + wn + ni * 8;
                float2 v0 = make_float2(acc[mi][ni][0], acc[mi][ni][1]);
                float2 v1 = make_float2(acc[mi][ni][2], acc[mi][ni][3]);
                *reinterpret_cast<float2*>(C + (size_t)(mb + er) * Cc + nb + ec) = v0;
                *reinterpret_cast<float2*>(C + (size_t)(mb + 8 + er) * Cc + nb + ec) = v1;
            }
        }
    }
}

// ---------------------------------------------------------------------------
// WKV pass 1: per-segment partial (num, den) with convention
//   local = sum_i ew^(L-1-i) * e^{k_i} * [v_i, 1]
// One thread per (seg, b, c). Full occupancy (NSEG*B*C = 262144 threads).
// ---------------------------------------------------------------------------
__global__ void wkv_pass1(const __half* __restrict__ kbuf,
                          const __half* __restrict__ rbuf,
                          const float* __restrict__ td,
                          float* __restrict__ pnum,
                          float* __restrict__ pden)
{
    const int idx = blockIdx.x * blockDim.x + threadIdx.x;
    if (idx >= NSEG * LANES) return;
    const int c   = idx & (Cc - 1);
    const int b   = (idx >> 10) & (Bc - 1);
    const int seg = idx >> 14;

    const float ew = __expf(-__expf(td[c]));
    const size_t base = ((size_t)b * Tc + (size_t)seg * SEGL) * Cc + c;
    const __half* kp = kbuf + base;
    const __half* rp = rbuf + base;

    float num = 0.f, den = 0.f;
    for (int t = 0; t < SEGL; t += 4) {
        float kt[4], rt[4];
#pragma unroll
        for (int j = 0; j < 4; j++) {
            kt[j] = __half2float(kp[(size_t)(t + j) * Cc]);
            rt[j] = __half2float(rp[(size_t)(t + j) * Cc]);
        }
#pragma unroll
        for (int j = 0; j < 4; j++) {
            const float ek = __expf(kt[j]);
            num = fmaf(ew, num, ek * rt[j]);
            den = fmaf(ew, den, ek);
        }
    }
    pnum[idx] = num;
    pden[idx] = den;
}

// ---------------------------------------------------------------------------
// WKV pass 2: prefix-combine carries, then rescan segment emitting
// o = sigmoid(r) * y as fp16.
// ---------------------------------------------------------------------------
__global__ void wkv_pass2(const __half* __restrict__ kbuf,
                          const __half* __restrict__ rbuf,
                          const float* __restrict__ td,
                          const float* __restrict__ tf,
                          const float* __restrict__ pnum,
                          const float* __restrict__ pden,
                          __half* __restrict__ obuf)
{
    const int idx = blockIdx.x * blockDim.x + threadIdx.x;
    if (idx >= NSEG * LANES) return;
    const int c   = idx & (Cc - 1);
    const int b   = (idx >> 10) & (Bc - 1);
    const int bc  = idx & (LANES - 1);
    const int seg = idx >> 14;

    const float etd = __expf(td[c]);
    const float ew  = __expf(-etd);
    const float ewL = __expf(-etd * (float)SEGL);   // ew^SEGL
    const float eu  = __expf(tf[c]);

    // prefix state at segment start
    float num = 0.f, den = 0.f;
    for (int s = 0; s < seg; s++) {
        num = fmaf(ewL, num, pnum[s * LANES + bc]);
        den = fmaf(ewL, den, pden[s * LANES + bc]);
    }

    const size_t base = ((size_t)b * Tc + (size_t)seg * SEGL) * Cc + c;
    const __half* kp = kbuf + base;
    const __half* rp = rbuf + base;
    __half*       op = obuf + base;

    for (int t = 0; t < SEGL; t += 4) {
        float kt[4], rt[4];
#pragma unroll
        for (int j = 0; j < 4; j++) {
            kt[j] = __half2float(kp[(size_t)(t + j) * Cc]);
            rt[j] = __half2float(rp[(size_t)(t + j) * Cc]);
        }
#pragma unroll
        for (int j = 0; j < 4; j++) {
            const float ek  = __expf(kt[j]);
            const float euk = eu * ek;
            const float y   = __fdividef(fmaf(euk, rt[j], num), den + euk);
            num = fmaf(ew, num, ek * rt[j]);
            den = fmaf(ew, den, ek);
            const float sg  = __fdividef(1.f, 1.f + __expf(-rt[j]));
            op[(size_t)(t + j) * Cc] = __float2half(sg * y);
        }
    }
}

// ---------------------------------------------------------------------------
// Launch sequence (graph-capturable; default stream)
// ---------------------------------------------------------------------------
extern "C" void kernel_launch(void* const* d_in, const int* in_sizes, int n_in,
                              void* d_out, int out_size)
{
    const float* x  = (const float*)d_in[0];
    const float* Wk = (const float*)d_in[1];
    const float* Wr = (const float*)d_in[2];
    const float* Wo = (const float*)d_in[3];
    const float* td = (const float*)d_in[4];
    const float* tf = (const float*)d_in[5];
    float* out = (float*)d_out;

    __half *xh, *of, *wkhi, *wklo, *wrh, *woh, *pk, *pr;
    float *pn, *pd;
    cudaGetSymbolAddress((void**)&xh,   g_xh);
    cudaGetSymbolAddress((void**)&of,   g_of);
    cudaGetSymbolAddress((void**)&pk,   g_k);
    cudaGetSymbolAddress((void**)&pr,   g_r);
    cudaGetSymbolAddress((void**)&wkhi, g_wkhi);
    cudaGetSymbolAddress((void**)&wklo, g_wklo);
    cudaGetSymbolAddress((void**)&wrh,  g_wrh);
    cudaGetSymbolAddress((void**)&woh,  g_woh);
    cudaGetSymbolAddress((void**)&pn,   g_pn);
    cudaGetSymbolAddress((void**)&pd,   g_pd);

    cudaFuncSetAttribute(gemm_hmma, cudaFuncAttributeMaxDynamicSharedMemorySize,
                         GEMM_SMEM);

    const int nx4 = (Mc * Kc) / 4;
    const int nw4 = (Cc * Kc) / 4;
    cvt_kernel<<<nx4 / 256, 256>>>(x, xh, nx4);
    wcvt_kernel<<<nw4 / 256, 256>>>(Wk, Wr, Wo, wkhi, wklo, wrh, woh, nw4);

    // z=0: k = x*Wk^T (2-term);  z=1: r = x*Wr^T (1-term); both -> fp16
    dim3 grid_kr(Cc / 256, Mc / 128, 2);
    gemm_hmma<<<grid_kr, 256, GEMM_SMEM>>>(xh, wkhi, wklo, pk, wrh, pr, 0, 1);

    // segment-parallel wkv
    const int nthr = NSEG * LANES;
    wkv_pass1<<<nthr / 256, 256>>>(pk, pr, td, pn, pd);
    wkv_pass2<<<nthr / 256, 256>>>(pk, pr, td, tf, pn, pd, of);

    // out = o * Wo^T (1-term), fp32 output
    dim3 grid_o(Cc / 256, Mc / 128, 1);
    gemm_hmma<<<grid_o, 256, GEMM_SMEM>>>(of, nullptr, nullptr, nullptr, woh,
                                          out, 1, 0);
}

// round 9
// speedup vs baseline: 7.1459x; 1.2642x over previous
#include <cuda_runtime.h>
#include <cuda_fp16.h>
#include <cstdint>
#include <cstddef>

// Problem shape (fixed)
#define Bc 16
#define Tc 1024
#define Cc 1024
#define Kc 1024
#define Mc (Bc * Tc)   // 16384
#define NSEG 16
#define SEGL (Tc / NSEG)   // 64
#define LANES (Bc * Cc)    // 16384

// ---------------------------------------------------------------------------
// Scratch (__device__ globals; no cudaMalloc allowed)
// ---------------------------------------------------------------------------
__device__ __half g_xh [(size_t)Mc * Kc];     // x as fp16
__device__ __half g_of [(size_t)Mc * Kc];     // gated wkv output as fp16
__device__ __half g_k  [(size_t)Mc * Cc];     // k as fp16
__device__ __half g_r  [(size_t)Mc * Cc];     // r as fp16
__device__ __half g_wkh[Cc * Kc];             // Wk fp16
__device__ __half g_wrh[Cc * Kc];             // Wr fp16
__device__ __half g_woh[Cc * Kc];             // Wo fp16
__device__ float  g_pn [NSEG * LANES];        // per-segment partial num
__device__ float  g_pd [NSEG * LANES];        // per-segment partial den

// ---------------------------------------------------------------------------
// Base-ISA PTX helpers (compile for plain .target sm_103)
// ---------------------------------------------------------------------------
__device__ __forceinline__ uint32_t smem_u32(const void* p) {
    uint32_t a;
    asm("{ .reg .u64 t; cvta.to.shared.u64 t, %1; cvt.u32.u64 %0, t; }"
        : "=r"(a) : "l"(p));
    return a;
}
__device__ __forceinline__ void cp_async16(uint32_t dst, const void* src) {
    asm volatile("cp.async.cg.shared.global [%0], [%1], 16;"
                 :: "r"(dst), "l"(src));
}
__device__ __forceinline__ void cp_commit() {
    asm volatile("cp.async.commit_group;");
}
__device__ __forceinline__ void cp_wait2() {
    asm volatile("cp.async.wait_group 2;" ::: "memory");
}
__device__ __forceinline__ void cp_wait1() {
    asm volatile("cp.async.wait_group 1;" ::: "memory");
}
__device__ __forceinline__ void cp_wait0() {
    asm volatile("cp.async.wait_group 0;" ::: "memory");
}
__device__ __forceinline__ void ldm_x4(uint32_t* r, uint32_t addr) {
    asm volatile("ldmatrix.sync.aligned.m8n8.x4.shared.b16 {%0,%1,%2,%3}, [%4];"
                 : "=r"(r[0]), "=r"(r[1]), "=r"(r[2]), "=r"(r[3]) : "r"(addr));
}
__device__ __forceinline__ void mma_fp16(float* d, const uint32_t* a,
                                         const uint32_t* b) {
    asm volatile(
        "mma.sync.aligned.m16n8k16.row.col.f32.f16.f16.f32 "
        "{%0,%1,%2,%3}, {%4,%5,%6,%7}, {%8,%9}, {%0,%1,%2,%3};"
        : "+f"(d[0]), "+f"(d[1]), "+f"(d[2]), "+f"(d[3])
        : "r"(a[0]), "r"(a[1]), "r"(a[2]), "r"(a[3]), "r"(b[0]), "r"(b[1]));
}

// ---------------------------------------------------------------------------
// fp32 -> fp16 convert (x), vectorized
// ---------------------------------------------------------------------------
__global__ void cvt_kernel(const float* __restrict__ src,
                           __half* __restrict__ dst, int n4)
{
    int i = blockIdx.x * blockDim.x + threadIdx.x;
    if (i >= n4) return;
    float4 v = reinterpret_cast<const float4*>(src)[i];
    reinterpret_cast<__half2*>(dst)[2 * i]     = __floats2half2_rn(v.x, v.y);
    reinterpret_cast<__half2*>(dst)[2 * i + 1] = __floats2half2_rn(v.z, v.w);
}

// ---------------------------------------------------------------------------
// Fused weight prep: Wk, Wr, Wo -> fp16
// ---------------------------------------------------------------------------
__global__ void wcvt_kernel(const float* __restrict__ Wk,
                            const float* __restrict__ Wr,
                            const float* __restrict__ Wo,
                            __half* __restrict__ wkh,
                            __half* __restrict__ wrh,
                            __half* __restrict__ woh,
                            int n4)
{
    int i = blockIdx.x * blockDim.x + threadIdx.x;
    if (i >= n4) return;
    {
        float4 v = reinterpret_cast<const float4*>(Wk)[i];
        reinterpret_cast<__half2*>(wkh)[2 * i]     = __floats2half2_rn(v.x, v.y);
        reinterpret_cast<__half2*>(wkh)[2 * i + 1] = __floats2half2_rn(v.z, v.w);
    }
    {
        float4 v = reinterpret_cast<const float4*>(Wr)[i];
        reinterpret_cast<__half2*>(wrh)[2 * i]     = __floats2half2_rn(v.x, v.y);
        reinterpret_cast<__half2*>(wrh)[2 * i + 1] = __floats2half2_rn(v.z, v.w);
    }
    {
        float4 v = reinterpret_cast<const float4*>(Wo)[i];
        reinterpret_cast<__half2*>(woh)[2 * i]     = __floats2half2_rn(v.x, v.y);
        reinterpret_cast<__half2*>(woh)[2 * i + 1] = __floats2half2_rn(v.z, v.w);
    }
}

// ---------------------------------------------------------------------------
// HMMA fp16 NT GEMM: C[M,1024] = A[M,K] * B[N,K]^T.
// CTA tile 128(M) x 256(N), K-chunk 64 (128B swizzled rows), 8 warps in a
// 2(m) x 4(n) grid -> warp tile 64x64. 4-stage cp.async pipeline.
// blockIdx.z selects (B0,C0)/(B1,C1); output fp16 or fp32 via half_out.
// ---------------------------------------------------------------------------
#define BK 64
#define B_OFF   16384               // A tile 128*128B
#define STAGE_B 49152               // A(16KB) + B(32KB)
#define NSTAGE  4
#define GEMM_SMEM (NSTAGE * STAGE_B)   // 196608
#define NCHUNK (Kc / BK)            // 16

__global__ __launch_bounds__(256, 1)
void gemm_hmma(const __half* __restrict__ A,
               const __half* __restrict__ B0,
               void* __restrict__ C0,
               const __half* __restrict__ B1,
               void* __restrict__ C1,
               int half_out)
{
    extern __shared__ char smem_raw[];
    const uint32_t sbase = smem_u32(smem_raw);

    const int tid  = threadIdx.x;
    const int wid  = tid >> 5;
    const int lane = tid & 31;

    const __half* B = blockIdx.z ? B1 : B0;
    void* Cmat      = blockIdx.z ? C1 : C0;

    const int m0 = blockIdx.y * 128;
    const int n0 = blockIdx.x * 256;

    const __half* Ap = A + (size_t)m0 * Kc;
    const __half* Bp = B + (size_t)n0 * Kc;

    // ---- cp.async segment maps ---------------------------------------------
    uint32_t sdstA[4], goffA[4];
#pragma unroll
    for (int i = 0; i < 4; i++) {
        const int sid = i * 256 + tid;        // 0..1023
        const int row = sid >> 3;             // 0..127
        const int s   = sid & 7;
        sdstA[i] = row * 128 + ((s ^ (row & 7)) << 4);
        goffA[i] = row * Kc + s * 8;
    }
    uint32_t sdstB[8], goffB[8];
#pragma unroll
    for (int j = 0; j < 8; j++) {
        const int sid = j * 256 + tid;        // 0..2047
        const int row = sid >> 3;             // 0..255
        const int s   = sid & 7;
        sdstB[j] = B_OFF + row * 128 + ((s ^ (row & 7)) << 4);
        goffB[j] = row * Kc + s * 8;
    }

    // ---- warp tiling -------------------------------------------------------
    const int wm = (wid & 1) * 64;
    const int wn = (wid >> 1) * 64;

    float acc[4][8][4];
#pragma unroll
    for (int mi = 0; mi < 4; mi++)
#pragma unroll
        for (int ni = 0; ni < 8; ni++)
#pragma unroll
            for (int j = 0; j < 4; j++) acc[mi][ni][j] = 0.f;

    const int a_row = wm + (lane & 15);
    const int a_ks  = lane >> 4;
    const int b_row = wn + (lane & 7) + ((lane >> 4) << 3);
    const int b_ks  = (lane >> 3) & 1;

#define ISSUE_CHUNK(chunk) do {                                                \
    const uint32_t _buf = sbase + ((chunk) & (NSTAGE - 1)) * STAGE_B;          \
    const int _ko = (chunk) * BK;                                              \
    _Pragma("unroll")                                                          \
    for (int i = 0; i < 4; i++)                                                \
        cp_async16(_buf + sdstA[i], Ap + goffA[i] + _ko);                      \
    _Pragma("unroll")                                                          \
    for (int j = 0; j < 8; j++)                                                \
        cp_async16(_buf + sdstB[j], Bp + goffB[j] + _ko);                      \
    cp_commit();                                                               \
} while (0)

    ISSUE_CHUNK(0);
    ISSUE_CHUNK(1);
    ISSUE_CHUNK(2);

    for (int c = 0; c < NCHUNK; ++c) {
        if (c <= NCHUNK - 3)      cp_wait2();
        else if (c == NCHUNK - 2) cp_wait1();
        else                      cp_wait0();
        __syncthreads();

        const uint32_t buf = sbase + (c & (NSTAGE - 1)) * STAGE_B;
#pragma unroll
        for (int ks = 0; ks < 4; ks++) {
            uint32_t af[4][4];
#pragma unroll
            for (int mi = 0; mi < 4; mi++) {
                const int row = a_row + mi * 16;
                const int sg  = (ks * 2 + a_ks) ^ (row & 7);
                ldm_x4(af[mi], buf + row * 128 + (sg << 4));
            }
#pragma unroll
            for (int ni = 0; ni < 4; ni++) {
                const int row = b_row + ni * 16;
                const int sg  = (ks * 2 + b_ks) ^ (row & 7);
                uint32_t bh[4];
                ldm_x4(bh, buf + B_OFF + row * 128 + (sg << 4));
#pragma unroll
                for (int mi = 0; mi < 4; mi++) {
                    mma_fp16(acc[mi][2 * ni],     af[mi], bh);
                    mma_fp16(acc[mi][2 * ni + 1], af[mi], bh + 2);
                }
            }
        }
        __syncthreads();
        if (c + 3 < NCHUNK) {
            ISSUE_CHUNK(c + 3);
        }
    }
#undef ISSUE_CHUNK

    // ---- epilogue ----------------------------------------------------------
    const int er = lane >> 2;
    const int ec = (lane & 3) * 2;
    if (half_out) {
        __half* C = (__half*)Cmat;
#pragma unroll
        for (int mi = 0; mi < 4; mi++) {
            const int mb = m0 + wm + mi * 16;
#pragma unroll
            for (int ni = 0; ni < 8; ni++) {
                const int nb = n0 + wn + ni * 8;
                *reinterpret_cast<__half2*>(C + (size_t)(mb + er) * Cc + nb + ec) =
                    __floats2half2_rn(acc[mi][ni][0], acc[mi][ni][1]);
                *reinterpret_cast<__half2*>(C + (size_t)(mb + 8 + er) * Cc + nb + ec) =
                    __floats2half2_rn(acc[mi][ni][2], acc[mi][ni][3]);
            }
        }
    } else {
        float* C = (float*)Cmat;
#pragma unroll
        for (int mi = 0; mi < 4; mi++) {
            const int mb = m0 + wm + mi * 16;
#pragma unroll
            for (int ni = 0; ni < 8; ni++) {
                const int nb = n0 + wn + ni * 8;
                float2 v0 = make_float2(acc[mi][ni][0], acc[mi][ni][1]);
                float2 v1 = make_float2(acc[mi][ni][2], acc[mi][ni][3]);
                *reinterpret_cast<float2*>(C + (size_t)(mb + er) * Cc + nb + ec) = v0;
                *reinterpret_cast<float2*>(C + (size_t)(mb + 8 + er) * Cc + nb + ec) = v1;
            }
        }
    }
}

// ---------------------------------------------------------------------------
// WKV pass 1: per-segment partial (num, den):
//   local = sum_i ew^(L-1-i) * e^{k_i} * [v_i, 1]
// One thread per (seg, b, c); NSEG*LANES = 262144 threads (full occupancy).
// ---------------------------------------------------------------------------
__global__ void wkv_pass1(const __half* __restrict__ kbuf,
                          const __half* __restrict__ rbuf,
                          const float* __restrict__ td,
                          float* __restrict__ pnum,
                          float* __restrict__ pden)
{
    const int idx = blockIdx.x * blockDim.x + threadIdx.x;
    if (idx >= NSEG * LANES) return;
    const int c   = idx & (Cc - 1);
    const int b   = (idx >> 10) & (Bc - 1);
    const int seg = idx >> 14;

    const float ew = __expf(-__expf(td[c]));
    const size_t base = ((size_t)b * Tc + (size_t)seg * SEGL) * Cc + c;
    const __half* kp = kbuf + base;
    const __half* rp = rbuf + base;

    float num = 0.f, den = 0.f;
    for (int t = 0; t < SEGL; t += 4) {
        float kt[4], rt[4];
#pragma unroll
        for (int j = 0; j < 4; j++) {
            kt[j] = __half2float(kp[(size_t)(t + j) * Cc]);
            rt[j] = __half2float(rp[(size_t)(t + j) * Cc]);
        }
#pragma unroll
        for (int j = 0; j < 4; j++) {
            const float ek = __expf(kt[j]);
            num = fmaf(ew, num, ek * rt[j]);
            den = fmaf(ew, den, ek);
        }
    }
    pnum[idx] = num;
    pden[idx] = den;
}

// ---------------------------------------------------------------------------
// WKV pass 2: prefix-combine segment carries, rescan emitting
// o = sigmoid(r) * y as fp16.
// ---------------------------------------------------------------------------
__global__ void wkv_pass2(const __half* __restrict__ kbuf,
                          const __half* __restrict__ rbuf,
                          const float* __restrict__ td,
                          const float* __restrict__ tf,
                          const float* __restrict__ pnum,
                          const float* __restrict__ pden,
                          __half* __restrict__ obuf)
{
    const int idx = blockIdx.x * blockDim.x + threadIdx.x;
    if (idx >= NSEG * LANES) return;
    const int c   = idx & (Cc - 1);
    const int b   = (idx >> 10) & (Bc - 1);
    const int bc  = idx & (LANES - 1);
    const int seg = idx >> 14;

    const float etd = __expf(td[c]);
    const float ew  = __expf(-etd);
    const float ewL = __expf(-etd * (float)SEGL);
    const float eu  = __expf(tf[c]);

    float num = 0.f, den = 0.f;
    for (int s = 0; s < seg; s++) {
        num = fmaf(ewL, num, pnum[s * LANES + bc]);
        den = fmaf(ewL, den, pden[s * LANES + bc]);
    }

    const size_t base = ((size_t)b * Tc + (size_t)seg * SEGL) * Cc + c;
    const __half* kp = kbuf + base;
    const __half* rp = rbuf + base;
    __half*       op = obuf + base;

    for (int t = 0; t < SEGL; t += 4) {
        float kt[4], rt[4];
#pragma unroll
        for (int j = 0; j < 4; j++) {
            kt[j] = __half2float(kp[(size_t)(t + j) * Cc]);
            rt[j] = __half2float(rp[(size_t)(t + j) * Cc]);
        }
#pragma unroll
        for (int j = 0; j < 4; j++) {
            const float ek  = __expf(kt[j]);
            const float euk = eu * ek;
            const float y   = __fdividef(fmaf(euk, rt[j], num), den + euk);
            num = fmaf(ew, num, ek * rt[j]);
            den = fmaf(ew, den, ek);
            const float sg  = __fdividef(1.f, 1.f + __expf(-rt[j]));
            op[(size_t)(t + j) * Cc] = __float2half(sg * y);
        }
    }
}

// ---------------------------------------------------------------------------
// Launch sequence (graph-capturable; default stream)
// ---------------------------------------------------------------------------
extern "C" void kernel_launch(void* const* d_in, const int* in_sizes, int n_in,
                              void* d_out, int out_size)
{
    const float* x  = (const float*)d_in[0];
    const float* Wk = (const float*)d_in[1];
    const float* Wr = (const float*)d_in[2];
    const float* Wo = (const float*)d_in[3];
    const float* td = (const float*)d_in[4];
    const float* tf = (const float*)d_in[5];
    float* out = (float*)d_out;

    __half *xh, *of, *wkh, *wrh, *woh, *pk, *pr;
    float *pn, *pd;
    cudaGetSymbolAddress((void**)&xh,  g_xh);
    cudaGetSymbolAddress((void**)&of,  g_of);
    cudaGetSymbolAddress((void**)&pk,  g_k);
    cudaGetSymbolAddress((void**)&pr,  g_r);
    cudaGetSymbolAddress((void**)&wkh, g_wkh);
    cudaGetSymbolAddress((void**)&wrh, g_wrh);
    cudaGetSymbolAddress((void**)&woh, g_woh);
    cudaGetSymbolAddress((void**)&pn,  g_pn);
    cudaGetSymbolAddress((void**)&pd,  g_pd);

    cudaFuncSetAttribute(gemm_hmma, cudaFuncAttributeMaxDynamicSharedMemorySize,
                         GEMM_SMEM);

    const int nx4 = (Mc * Kc) / 4;
    const int nw4 = (Cc * Kc) / 4;
    cvt_kernel<<<nx4 / 256, 256>>>(x, xh, nx4);
    wcvt_kernel<<<nw4 / 256, 256>>>(Wk, Wr, Wo, wkh, wrh, woh, nw4);

    // z=0: k = x*Wk^T ; z=1: r = x*Wr^T ; both -> fp16
    dim3 grid_kr(Cc / 256, Mc / 128, 2);
    gemm_hmma<<<grid_kr, 256, GEMM_SMEM>>>(xh, wkh, pk, wrh, pr, 1);

    // segment-parallel wkv
    const int nthr = NSEG * LANES;
    wkv_pass1<<<nthr / 256, 256>>>(pk, pr, td, pn, pd);
    wkv_pass2<<<nthr / 256, 256>>>(pk, pr, td, tf, pn, pd, of);

    // out = o * Wo^T, fp32 output
    dim3 grid_o(Cc / 256, Mc / 128, 1);
    gemm_hmma<<<grid_o, 256, GEMM_SMEM>>>(of, woh, out, woh, out, 0);
}